// round 12
// baseline (speedup 1.0000x reference)
#include <cuda_runtime.h>
#include <cuda_fp16.h>
#include <cstdint>

// MeanAggregator: ragged segment-mean, sorted int32 segment_ids.
// fp16-staged features (256B rows). Warp-per-node TMA bulk-gather:
// each stage gathers up to 16 rows via cp.async.bulk (one 256B row per lane
// instruction, mbarrier completion), double-buffered. In-flight data lives
// in smem, not registers -> deep MLP at regs~32.

#define D_FEAT 128
#define VEC_PER_ROW (D_FEAT / 4)
#define WARPS_PER_BLOCK 4
#define MAX_NODES 50000
#define EPW 16                      // edges (rows) per stage
#define ROW_BYTES 256

__device__ __half2 g_feat_h2[MAX_NODES * (D_FEAT / 2)];

__global__ void convert_f32_to_f16(const float2* __restrict__ in, int n2)
{
    int i = blockIdx.x * blockDim.x + threadIdx.x;
    if (i < n2) g_feat_h2[i] = __float22half2_rn(in[i]);
}

__device__ __forceinline__ unsigned smem_u32(const void* p)
{
    return (unsigned)__cvta_generic_to_shared(p);
}

__device__ __forceinline__ void mbar_init(unsigned a, unsigned count)
{
    asm volatile("mbarrier.init.shared.b64 [%0], %1;" :: "r"(a), "r"(count) : "memory");
}

__device__ __forceinline__ void mbar_expect_tx(unsigned a, unsigned bytes)
{
    asm volatile("mbarrier.arrive.expect_tx.shared.b64 _, [%0], %1;"
                 :: "r"(a), "r"(bytes) : "memory");
}

__device__ __forceinline__ void mbar_wait(unsigned a, unsigned parity)
{
    asm volatile(
        "{\n\t"
        ".reg .pred P;\n\t"
        "WAIT_%=:\n\t"
        "mbarrier.try_wait.parity.shared.b64 P, [%0], %1;\n\t"
        "@P bra DONE_%=;\n\t"
        "bra WAIT_%=;\n\t"
        "DONE_%=:\n\t"
        "}"
        :: "r"(a), "r"(parity) : "memory");
}

__device__ __forceinline__ void bulk_ld(unsigned dst, const void* src,
                                        unsigned bytes, unsigned mbar)
{
    asm volatile(
        "cp.async.bulk.shared::cluster.global.mbarrier::complete_tx::bytes "
        "[%0], [%1], %2, [%3];"
        :: "r"(dst), "l"(src), "r"(bytes), "r"(mbar) : "memory");
}

__global__ void __launch_bounds__(128)
seg_mean_tma_kernel(const int* __restrict__ nbr,
                    const int* __restrict__ sid,
                    float* __restrict__ out,
                    int n_nodes, int n_edges)
{
    __shared__ int bounds[WARPS_PER_BLOCK + 1];
    __shared__ __align__(8) unsigned long long mbar[WARPS_PER_BLOCK][2];
    __shared__ __align__(128) unsigned char buf[WARPS_PER_BLOCK][2][EPW * ROW_BYTES];

    const int lane = threadIdx.x & 31;
    const int warp = threadIdx.x >> 5;
    const int node_base = blockIdx.x * WARPS_PER_BLOCK;

    if (lane == 0) {
        mbar_init(smem_u32(&mbar[warp][0]), 1);
        mbar_init(smem_u32(&mbar[warp][1]), 1);
        asm volatile("fence.proxy.async.shared::cta;" ::: "memory");
    }

    if (warp == 0 && lane <= WARPS_PER_BLOCK) {
        const int target = node_base + lane;
        int lo = 0, hi = n_edges;
        while (lo < hi) {
            int mid = (lo + hi) >> 1;
            if (__ldg(&sid[mid]) < target) lo = mid + 1; else hi = mid;
        }
        bounds[lane] = lo;
    }
    __syncthreads();   // bounds + mbarrier inits visible

    const int node = node_base + warp;
    if (node >= n_nodes) return;

    const int start = bounds[warp];
    const int end   = bounds[warp + 1];

    const unsigned char* __restrict__ featb = (const unsigned char*)g_feat_h2;
    const unsigned mb0 = smem_u32(&mbar[warp][0]);
    const unsigned mb1 = smem_u32(&mbar[warp][1]);
    const unsigned bb0 = smem_u32(&buf[warp][0][0]);
    const unsigned bb1 = smem_u32(&buf[warp][1][0]);

    float4 acc0 = make_float4(0.f, 0.f, 0.f, 0.f);
    float4 acc1 = make_float4(0.f, 0.f, 0.f, 0.f);

    // ---- issue helper (inlined twice below) ----
    // lane < cnt: gather row nbr[e+lane] into stage buffer slot `lane`.
#define ISSUE_STAGE(MB, BB, E, CNT)                                          \
    do {                                                                     \
        int _idx = 0;                                                        \
        if (lane < (CNT)) _idx = __ldg(&nbr[(E) + lane]);                    \
        if (lane == 0) mbar_expect_tx((MB), (unsigned)(CNT) * ROW_BYTES);    \
        __syncwarp();                                                        \
        if (lane < (CNT))                                                    \
            bulk_ld((BB) + lane * ROW_BYTES,                                 \
                    featb + (size_t)_idx * ROW_BYTES, ROW_BYTES, (MB));      \
    } while (0)

    int e = start;
    int cur = 0;
    unsigned phase0 = 0, phase1 = 0;

    int cnt_cur = (end - e) < EPW ? (end - e) : EPW;
    if (cnt_cur > 0) {
        ISSUE_STAGE(mb0, bb0, e, cnt_cur);
        e += cnt_cur;
    }

    while (cnt_cur > 0) {
        int rem = end - e;
        int cnt_nxt = rem < EPW ? rem : EPW;
        if (cnt_nxt > 0) {
            if (cur == 0) ISSUE_STAGE(mb1, bb1, e, cnt_nxt);
            else          ISSUE_STAGE(mb0, bb0, e, cnt_nxt);
            e += cnt_nxt;
        }

        // Wait for current stage.
        if (cur == 0) { mbar_wait(mb0, phase0); phase0 ^= 1; }
        else          { mbar_wait(mb1, phase1); phase1 ^= 1; }

        // Consume: lane reads its 8B column slice of each gathered row.
        const unsigned char* bp = (cur == 0) ? &buf[warp][0][0] : &buf[warp][1][0];
        const unsigned char* lp = bp + lane * 8;
        for (int j = 0; j < cnt_cur; j++) {
            uint2 v = *(const uint2*)(lp + j * ROW_BYTES);
            float2 a = __half22float2(*(__half2*)&v.x);
            float2 b = __half22float2(*(__half2*)&v.y);
            if (j & 1) {
                acc1.x += a.x; acc1.y += a.y; acc1.z += b.x; acc1.w += b.y;
            } else {
                acc0.x += a.x; acc0.y += a.y; acc0.z += b.x; acc0.w += b.y;
            }
        }
        // Order our smem reads before the async-proxy writes of the next
        // issue into this same buffer.
        asm volatile("fence.proxy.async.shared::cta;" ::: "memory");

        cnt_cur = cnt_nxt;
        cur ^= 1;
    }
#undef ISSUE_STAGE

    acc0.x += acc1.x; acc0.y += acc1.y; acc0.z += acc1.z; acc0.w += acc1.w;

    const int cnt = end - start;
    const float inv = (cnt > 0) ? (1.0f / (float)cnt) : 0.0f;
    acc0.x *= inv; acc0.y *= inv; acc0.z *= inv; acc0.w *= inv;

    ((float4*)out)[node * VEC_PER_ROW + lane] = acc0;
}

// Fallback f32 path (only if n_nodes exceeds the static fp16 buffer).
__global__ void __launch_bounds__(256)
seg_mean_f32_kernel(const float* __restrict__ feat,
                    const int* __restrict__ nbr,
                    const int* __restrict__ sid,
                    float* __restrict__ out,
                    int n_nodes, int n_edges)
{
    __shared__ int bounds[9];
    const int lane = threadIdx.x & 31;
    const int warp = threadIdx.x >> 5;
    const int node_base = blockIdx.x * 8;

    if (warp == 0 && lane <= 8) {
        const int target = node_base + lane;
        int lo = 0, hi = n_edges;
        while (lo < hi) {
            int mid = (lo + hi) >> 1;
            if (__ldg(&sid[mid]) < target) lo = mid + 1; else hi = mid;
        }
        bounds[lane] = lo;
    }
    __syncthreads();

    const int node = node_base + warp;
    if (node >= n_nodes) return;
    const int start = bounds[warp];
    const int end   = bounds[warp + 1];

    const float4* __restrict__ featv = (const float4*)feat;
    float4 acc0 = make_float4(0.f, 0.f, 0.f, 0.f);
    float4 acc1 = make_float4(0.f, 0.f, 0.f, 0.f);

    int e = start;
    for (; e + 4 <= end; e += 4) {
        int i0 = __ldg(&nbr[e]);
        int i1 = __ldg(&nbr[e + 1]);
        int i2 = __ldg(&nbr[e + 2]);
        int i3 = __ldg(&nbr[e + 3]);
        float4 v0 = __ldg(&featv[i0 * VEC_PER_ROW + lane]);
        float4 v1 = __ldg(&featv[i1 * VEC_PER_ROW + lane]);
        float4 v2 = __ldg(&featv[i2 * VEC_PER_ROW + lane]);
        float4 v3 = __ldg(&featv[i3 * VEC_PER_ROW + lane]);
        acc0.x += v0.x; acc0.y += v0.y; acc0.z += v0.z; acc0.w += v0.w;
        acc1.x += v1.x; acc1.y += v1.y; acc1.z += v1.z; acc1.w += v1.w;
        acc0.x += v2.x; acc0.y += v2.y; acc0.z += v2.z; acc0.w += v2.w;
        acc1.x += v3.x; acc1.y += v3.y; acc1.z += v3.z; acc1.w += v3.w;
    }
    for (; e < end; e++) {
        int i0 = __ldg(&nbr[e]);
        float4 v0 = __ldg(&featv[i0 * VEC_PER_ROW + lane]);
        acc0.x += v0.x; acc0.y += v0.y; acc0.z += v0.z; acc0.w += v0.w;
    }
    acc0.x += acc1.x; acc0.y += acc1.y; acc0.z += acc1.z; acc0.w += acc1.w;

    const int cnt = end - start;
    const float inv = (cnt > 0) ? (1.0f / (float)cnt) : 0.0f;
    acc0.x *= inv; acc0.y *= inv; acc0.z *= inv; acc0.w *= inv;
    ((float4*)out)[node * VEC_PER_ROW + lane] = acc0;
}

extern "C" void kernel_launch(void* const* d_in, const int* in_sizes, int n_in,
                              void* d_out, int out_size)
{
    const float* feat = (const float*)d_in[0];   // [N, 128] f32
    const int*   nbr  = (const int*)d_in[1];     // [E] i32
    const int*   sid  = (const int*)d_in[2];     // [E] i32, sorted
    float*       out  = (float*)d_out;           // [N, 128] f32

    const int n_edges = in_sizes[1];
    const int n_nodes = out_size / D_FEAT;

    if (n_nodes <= MAX_NODES) {
        const int n2 = n_nodes * (D_FEAT / 2);
        const int cthreads = 256;
        const int cblocks = (n2 + cthreads - 1) / cthreads;
        convert_f32_to_f16<<<cblocks, cthreads>>>((const float2*)feat, n2);
        const int blocks = (n_nodes + WARPS_PER_BLOCK - 1) / WARPS_PER_BLOCK;
        seg_mean_tma_kernel<<<blocks, 32 * WARPS_PER_BLOCK>>>(nbr, sid, out,
                                                              n_nodes, n_edges);
    } else {
        const int blocks = (n_nodes + 7) / 8;
        seg_mean_f32_kernel<<<blocks, 256>>>(feat, nbr, sid, out, n_nodes, n_edges);
    }
}

// round 13
// speedup vs baseline: 1.0016x; 1.0016x over previous
#include <cuda_runtime.h>
#include <cuda_fp16.h>
#include <cstdint>

// MeanAggregator: ragged segment-mean, sorted int32 segment_ids.
// fp16-staged features (256B rows). Warp-per-node TMA bulk-gather:
// each stage gathers up to 16 rows via cp.async.bulk (one 256B row per lane
// instruction, mbarrier completion), double-buffered. In-flight data lives
// in smem, not registers -> deep MLP at regs~32.

#define D_FEAT 128
#define VEC_PER_ROW (D_FEAT / 4)
#define WARPS_PER_BLOCK 4
#define MAX_NODES 50000
#define EPW 16                      // edges (rows) per stage
#define ROW_BYTES 256

__device__ __half2 g_feat_h2[MAX_NODES * (D_FEAT / 2)];

__global__ void convert_f32_to_f16(const float2* __restrict__ in, int n2)
{
    int i = blockIdx.x * blockDim.x + threadIdx.x;
    if (i < n2) g_feat_h2[i] = __float22half2_rn(in[i]);
}

__device__ __forceinline__ unsigned smem_u32(const void* p)
{
    return (unsigned)__cvta_generic_to_shared(p);
}

__device__ __forceinline__ void mbar_init(unsigned a, unsigned count)
{
    asm volatile("mbarrier.init.shared.b64 [%0], %1;" :: "r"(a), "r"(count) : "memory");
}

__device__ __forceinline__ void mbar_expect_tx(unsigned a, unsigned bytes)
{
    asm volatile("mbarrier.arrive.expect_tx.shared.b64 _, [%0], %1;"
                 :: "r"(a), "r"(bytes) : "memory");
}

__device__ __forceinline__ void mbar_wait(unsigned a, unsigned parity)
{
    asm volatile(
        "{\n\t"
        ".reg .pred P;\n\t"
        "WAIT_%=:\n\t"
        "mbarrier.try_wait.parity.shared.b64 P, [%0], %1;\n\t"
        "@P bra DONE_%=;\n\t"
        "bra WAIT_%=;\n\t"
        "DONE_%=:\n\t"
        "}"
        :: "r"(a), "r"(parity) : "memory");
}

__device__ __forceinline__ void bulk_ld(unsigned dst, const void* src,
                                        unsigned bytes, unsigned mbar)
{
    asm volatile(
        "cp.async.bulk.shared::cluster.global.mbarrier::complete_tx::bytes "
        "[%0], [%1], %2, [%3];"
        :: "r"(dst), "l"(src), "r"(bytes), "r"(mbar) : "memory");
}

__global__ void __launch_bounds__(128)
seg_mean_tma_kernel(const int* __restrict__ nbr,
                    const int* __restrict__ sid,
                    float* __restrict__ out,
                    int n_nodes, int n_edges)
{
    __shared__ int bounds[WARPS_PER_BLOCK + 1];
    __shared__ __align__(8) unsigned long long mbar[WARPS_PER_BLOCK][2];
    __shared__ __align__(128) unsigned char buf[WARPS_PER_BLOCK][2][EPW * ROW_BYTES];

    const int lane = threadIdx.x & 31;
    const int warp = threadIdx.x >> 5;
    const int node_base = blockIdx.x * WARPS_PER_BLOCK;

    if (lane == 0) {
        mbar_init(smem_u32(&mbar[warp][0]), 1);
        mbar_init(smem_u32(&mbar[warp][1]), 1);
        asm volatile("fence.proxy.async.shared::cta;" ::: "memory");
    }

    if (warp == 0 && lane <= WARPS_PER_BLOCK) {
        const int target = node_base + lane;
        int lo = 0, hi = n_edges;
        while (lo < hi) {
            int mid = (lo + hi) >> 1;
            if (__ldg(&sid[mid]) < target) lo = mid + 1; else hi = mid;
        }
        bounds[lane] = lo;
    }
    __syncthreads();   // bounds + mbarrier inits visible

    const int node = node_base + warp;
    if (node >= n_nodes) return;

    const int start = bounds[warp];
    const int end   = bounds[warp + 1];

    const unsigned char* __restrict__ featb = (const unsigned char*)g_feat_h2;
    const unsigned mb0 = smem_u32(&mbar[warp][0]);
    const unsigned mb1 = smem_u32(&mbar[warp][1]);
    const unsigned bb0 = smem_u32(&buf[warp][0][0]);
    const unsigned bb1 = smem_u32(&buf[warp][1][0]);

    float4 acc0 = make_float4(0.f, 0.f, 0.f, 0.f);
    float4 acc1 = make_float4(0.f, 0.f, 0.f, 0.f);

    // ---- issue helper (inlined twice below) ----
    // lane < cnt: gather row nbr[e+lane] into stage buffer slot `lane`.
#define ISSUE_STAGE(MB, BB, E, CNT)                                          \
    do {                                                                     \
        int _idx = 0;                                                        \
        if (lane < (CNT)) _idx = __ldg(&nbr[(E) + lane]);                    \
        if (lane == 0) mbar_expect_tx((MB), (unsigned)(CNT) * ROW_BYTES);    \
        __syncwarp();                                                        \
        if (lane < (CNT))                                                    \
            bulk_ld((BB) + lane * ROW_BYTES,                                 \
                    featb + (size_t)_idx * ROW_BYTES, ROW_BYTES, (MB));      \
    } while (0)

    int e = start;
    int cur = 0;
    unsigned phase0 = 0, phase1 = 0;

    int cnt_cur = (end - e) < EPW ? (end - e) : EPW;
    if (cnt_cur > 0) {
        ISSUE_STAGE(mb0, bb0, e, cnt_cur);
        e += cnt_cur;
    }

    while (cnt_cur > 0) {
        int rem = end - e;
        int cnt_nxt = rem < EPW ? rem : EPW;
        if (cnt_nxt > 0) {
            if (cur == 0) ISSUE_STAGE(mb1, bb1, e, cnt_nxt);
            else          ISSUE_STAGE(mb0, bb0, e, cnt_nxt);
            e += cnt_nxt;
        }

        // Wait for current stage.
        if (cur == 0) { mbar_wait(mb0, phase0); phase0 ^= 1; }
        else          { mbar_wait(mb1, phase1); phase1 ^= 1; }

        // Consume: lane reads its 8B column slice of each gathered row.
        const unsigned char* bp = (cur == 0) ? &buf[warp][0][0] : &buf[warp][1][0];
        const unsigned char* lp = bp + lane * 8;
        for (int j = 0; j < cnt_cur; j++) {
            uint2 v = *(const uint2*)(lp + j * ROW_BYTES);
            float2 a = __half22float2(*(__half2*)&v.x);
            float2 b = __half22float2(*(__half2*)&v.y);
            if (j & 1) {
                acc1.x += a.x; acc1.y += a.y; acc1.z += b.x; acc1.w += b.y;
            } else {
                acc0.x += a.x; acc0.y += a.y; acc0.z += b.x; acc0.w += b.y;
            }
        }
        // Order our smem reads before the async-proxy writes of the next
        // issue into this same buffer.
        asm volatile("fence.proxy.async.shared::cta;" ::: "memory");

        cnt_cur = cnt_nxt;
        cur ^= 1;
    }
#undef ISSUE_STAGE

    acc0.x += acc1.x; acc0.y += acc1.y; acc0.z += acc1.z; acc0.w += acc1.w;

    const int cnt = end - start;
    const float inv = (cnt > 0) ? (1.0f / (float)cnt) : 0.0f;
    acc0.x *= inv; acc0.y *= inv; acc0.z *= inv; acc0.w *= inv;

    ((float4*)out)[node * VEC_PER_ROW + lane] = acc0;
}

// Fallback f32 path (only if n_nodes exceeds the static fp16 buffer).
__global__ void __launch_bounds__(256)
seg_mean_f32_kernel(const float* __restrict__ feat,
                    const int* __restrict__ nbr,
                    const int* __restrict__ sid,
                    float* __restrict__ out,
                    int n_nodes, int n_edges)
{
    __shared__ int bounds[9];
    const int lane = threadIdx.x & 31;
    const int warp = threadIdx.x >> 5;
    const int node_base = blockIdx.x * 8;

    if (warp == 0 && lane <= 8) {
        const int target = node_base + lane;
        int lo = 0, hi = n_edges;
        while (lo < hi) {
            int mid = (lo + hi) >> 1;
            if (__ldg(&sid[mid]) < target) lo = mid + 1; else hi = mid;
        }
        bounds[lane] = lo;
    }
    __syncthreads();

    const int node = node_base + warp;
    if (node >= n_nodes) return;
    const int start = bounds[warp];
    const int end   = bounds[warp + 1];

    const float4* __restrict__ featv = (const float4*)feat;
    float4 acc0 = make_float4(0.f, 0.f, 0.f, 0.f);
    float4 acc1 = make_float4(0.f, 0.f, 0.f, 0.f);

    int e = start;
    for (; e + 4 <= end; e += 4) {
        int i0 = __ldg(&nbr[e]);
        int i1 = __ldg(&nbr[e + 1]);
        int i2 = __ldg(&nbr[e + 2]);
        int i3 = __ldg(&nbr[e + 3]);
        float4 v0 = __ldg(&featv[i0 * VEC_PER_ROW + lane]);
        float4 v1 = __ldg(&featv[i1 * VEC_PER_ROW + lane]);
        float4 v2 = __ldg(&featv[i2 * VEC_PER_ROW + lane]);
        float4 v3 = __ldg(&featv[i3 * VEC_PER_ROW + lane]);
        acc0.x += v0.x; acc0.y += v0.y; acc0.z += v0.z; acc0.w += v0.w;
        acc1.x += v1.x; acc1.y += v1.y; acc1.z += v1.z; acc1.w += v1.w;
        acc0.x += v2.x; acc0.y += v2.y; acc0.z += v2.z; acc0.w += v2.w;
        acc1.x += v3.x; acc1.y += v3.y; acc1.z += v3.z; acc1.w += v3.w;
    }
    for (; e < end; e++) {
        int i0 = __ldg(&nbr[e]);
        float4 v0 = __ldg(&featv[i0 * VEC_PER_ROW + lane]);
        acc0.x += v0.x; acc0.y += v0.y; acc0.z += v0.z; acc0.w += v0.w;
    }
    acc0.x += acc1.x; acc0.y += acc1.y; acc0.z += acc1.z; acc0.w += acc1.w;

    const int cnt = end - start;
    const float inv = (cnt > 0) ? (1.0f / (float)cnt) : 0.0f;
    acc0.x *= inv; acc0.y *= inv; acc0.z *= inv; acc0.w *= inv;
    ((float4*)out)[node * VEC_PER_ROW + lane] = acc0;
}

extern "C" void kernel_launch(void* const* d_in, const int* in_sizes, int n_in,
                              void* d_out, int out_size)
{
    const float* feat = (const float*)d_in[0];   // [N, 128] f32
    const int*   nbr  = (const int*)d_in[1];     // [E] i32
    const int*   sid  = (const int*)d_in[2];     // [E] i32, sorted
    float*       out  = (float*)d_out;           // [N, 128] f32

    const int n_edges = in_sizes[1];
    const int n_nodes = out_size / D_FEAT;

    if (n_nodes <= MAX_NODES) {
        const int n2 = n_nodes * (D_FEAT / 2);
        const int cthreads = 256;
        const int cblocks = (n2 + cthreads - 1) / cthreads;
        convert_f32_to_f16<<<cblocks, cthreads>>>((const float2*)feat, n2);
        const int blocks = (n_nodes + WARPS_PER_BLOCK - 1) / WARPS_PER_BLOCK;
        seg_mean_tma_kernel<<<blocks, 32 * WARPS_PER_BLOCK>>>(nbr, sid, out,
                                                              n_nodes, n_edges);
    } else {
        const int blocks = (n_nodes + 7) / 8;
        seg_mean_f32_kernel<<<blocks, 256>>>(feat, nbr, sid, out, n_nodes, n_edges);
    }
}

// round 14
// speedup vs baseline: 1.8123x; 1.8094x over previous
#include <cuda_runtime.h>
#include <cuda_fp16.h>
#include <cstdint>

// MeanAggregator: ragged segment-mean, sorted int32 segment_ids.
// fp16-staged features (256B rows). Warp-per-node; the block cooperatively
// stages its whole index range into smem (coalesced) so the hot loop's only
// global traffic is the feature gathers (__ldcg). x4 unroll.

#define D_FEAT 128
#define VEC_PER_ROW (D_FEAT / 4)
#define WARPS_PER_BLOCK 8
#define MAX_NODES 50000
#define IDX_CAP 1024                 // staged indices per block (4KB)

__device__ __half2 g_feat_h2[MAX_NODES * (D_FEAT / 2)];

__global__ void convert_f32_to_f16(const float2* __restrict__ in, int n2)
{
    int i = blockIdx.x * blockDim.x + threadIdx.x;
    if (i < n2) g_feat_h2[i] = __float22half2_rn(in[i]);
}

__global__ void __launch_bounds__(256)
seg_mean_h16_kernel(const int* __restrict__ nbr,
                    const int* __restrict__ sid,
                    float* __restrict__ out,
                    int n_nodes, int n_edges)
{
    __shared__ int bounds[WARPS_PER_BLOCK + 1];
    __shared__ int sidx[IDX_CAP];

    const int lane = threadIdx.x & 31;
    const int warp = threadIdx.x >> 5;
    const int tid  = threadIdx.x;
    const int node_base = blockIdx.x * WARPS_PER_BLOCK;

    if (warp == 0 && lane <= WARPS_PER_BLOCK) {
        const int target = node_base + lane;
        int lo = 0, hi = n_edges;
        while (lo < hi) {
            int mid = (lo + hi) >> 1;
            if (__ldg(&sid[mid]) < target) lo = mid + 1; else hi = mid;
        }
        bounds[lane] = lo;
    }
    __syncthreads();

    const int blk_start = bounds[0];
    const int blk_end   = bounds[WARPS_PER_BLOCK];
    const int blk_total = blk_end - blk_start;
    const int staged    = blk_total < IDX_CAP ? blk_total : IDX_CAP;

    // Coalesced cooperative stage of the block's indices.
    for (int i = tid; i < staged; i += 256)
        sidx[i] = __ldg(&nbr[blk_start + i]);
    __syncthreads();

    const int node = node_base + warp;
    if (node >= n_nodes) return;

    const int start = bounds[warp];
    const int end   = bounds[warp + 1];

    const uint2* __restrict__ featq = (const uint2*)g_feat_h2;

    float4 acc0 = make_float4(0.f, 0.f, 0.f, 0.f);
    float4 acc1 = make_float4(0.f, 0.f, 0.f, 0.f);

    // Portion of this warp's range that is staged in smem.
    const int s_begin = start - blk_start;           // >= 0
    const int s_end_full = end - blk_start;
    const int s_end = s_end_full < staged ? s_end_full : staged;

    int j = s_begin;
    for (; j + 4 <= s_end; j += 4) {
        int i0 = sidx[j];
        int i1 = sidx[j + 1];
        int i2 = sidx[j + 2];
        int i3 = sidx[j + 3];
        uint2 r0 = __ldcg(&featq[i0 * 32 + lane]);
        uint2 r1 = __ldcg(&featq[i1 * 32 + lane]);
        uint2 r2 = __ldcg(&featq[i2 * 32 + lane]);
        uint2 r3 = __ldcg(&featq[i3 * 32 + lane]);

        float2 a, b;
        a = __half22float2(*(__half2*)&r0.x); b = __half22float2(*(__half2*)&r0.y);
        acc0.x += a.x; acc0.y += a.y; acc0.z += b.x; acc0.w += b.y;
        a = __half22float2(*(__half2*)&r1.x); b = __half22float2(*(__half2*)&r1.y);
        acc1.x += a.x; acc1.y += a.y; acc1.z += b.x; acc1.w += b.y;
        a = __half22float2(*(__half2*)&r2.x); b = __half22float2(*(__half2*)&r2.y);
        acc0.x += a.x; acc0.y += a.y; acc0.z += b.x; acc0.w += b.y;
        a = __half22float2(*(__half2*)&r3.x); b = __half22float2(*(__half2*)&r3.y);
        acc1.x += a.x; acc1.y += a.y; acc1.z += b.x; acc1.w += b.y;
    }
    for (; j < s_end; j++) {
        int i0 = sidx[j];
        uint2 r0 = __ldcg(&featq[i0 * 32 + lane]);
        float2 a = __half22float2(*(__half2*)&r0.x);
        float2 b = __half22float2(*(__half2*)&r0.y);
        acc0.x += a.x; acc0.y += a.y; acc0.z += b.x; acc0.w += b.y;
    }
    // Overflow (block range exceeded IDX_CAP): direct index loads.
    for (int e = blk_start + (s_end > s_begin ? s_end : s_begin); e < end; e++) {
        if (e < blk_start + s_end_full && e >= blk_start + s_end) {
            int i0 = __ldg(&nbr[e]);
            uint2 r0 = __ldcg(&featq[i0 * 32 + lane]);
            float2 a = __half22float2(*(__half2*)&r0.x);
            float2 b = __half22float2(*(__half2*)&r0.y);
            acc0.x += a.x; acc0.y += a.y; acc0.z += b.x; acc0.w += b.y;
        }
    }

    acc0.x += acc1.x; acc0.y += acc1.y; acc0.z += acc1.z; acc0.w += acc1.w;

    const int cnt = end - start;
    const float inv = (cnt > 0) ? (1.0f / (float)cnt) : 0.0f;
    acc0.x *= inv; acc0.y *= inv; acc0.z *= inv; acc0.w *= inv;

    ((float4*)out)[node * VEC_PER_ROW + lane] = acc0;
}

// Fallback f32 path (only if n_nodes exceeds the static fp16 buffer).
__global__ void __launch_bounds__(256)
seg_mean_f32_kernel(const float* __restrict__ feat,
                    const int* __restrict__ nbr,
                    const int* __restrict__ sid,
                    float* __restrict__ out,
                    int n_nodes, int n_edges)
{
    __shared__ int bounds[9];
    const int lane = threadIdx.x & 31;
    const int warp = threadIdx.x >> 5;
    const int node_base = blockIdx.x * 8;

    if (warp == 0 && lane <= 8) {
        const int target = node_base + lane;
        int lo = 0, hi = n_edges;
        while (lo < hi) {
            int mid = (lo + hi) >> 1;
            if (__ldg(&sid[mid]) < target) lo = mid + 1; else hi = mid;
        }
        bounds[lane] = lo;
    }
    __syncthreads();

    const int node = node_base + warp;
    if (node >= n_nodes) return;
    const int start = bounds[warp];
    const int end   = bounds[warp + 1];

    const float4* __restrict__ featv = (const float4*)feat;
    float4 acc0 = make_float4(0.f, 0.f, 0.f, 0.f);
    float4 acc1 = make_float4(0.f, 0.f, 0.f, 0.f);

    int e = start;
    for (; e + 4 <= end; e += 4) {
        int i0 = __ldg(&nbr[e]);
        int i1 = __ldg(&nbr[e + 1]);
        int i2 = __ldg(&nbr[e + 2]);
        int i3 = __ldg(&nbr[e + 3]);
        float4 v0 = __ldg(&featv[i0 * VEC_PER_ROW + lane]);
        float4 v1 = __ldg(&featv[i1 * VEC_PER_ROW + lane]);
        float4 v2 = __ldg(&featv[i2 * VEC_PER_ROW + lane]);
        float4 v3 = __ldg(&featv[i3 * VEC_PER_ROW + lane]);
        acc0.x += v0.x; acc0.y += v0.y; acc0.z += v0.z; acc0.w += v0.w;
        acc1.x += v1.x; acc1.y += v1.y; acc1.z += v1.z; acc1.w += v1.w;
        acc0.x += v2.x; acc0.y += v2.y; acc0.z += v2.z; acc0.w += v2.w;
        acc1.x += v3.x; acc1.y += v3.y; acc1.z += v3.z; acc1.w += v3.w;
    }
    for (; e < end; e++) {
        int i0 = __ldg(&nbr[e]);
        float4 v0 = __ldg(&featv[i0 * VEC_PER_ROW + lane]);
        acc0.x += v0.x; acc0.y += v0.y; acc0.z += v0.z; acc0.w += v0.w;
    }
    acc0.x += acc1.x; acc0.y += acc1.y; acc0.z += acc1.z; acc0.w += acc1.w;

    const int cnt = end - start;
    const float inv = (cnt > 0) ? (1.0f / (float)cnt) : 0.0f;
    acc0.x *= inv; acc0.y *= inv; acc0.z *= inv; acc0.w *= inv;
    ((float4*)out)[node * VEC_PER_ROW + lane] = acc0;
}

extern "C" void kernel_launch(void* const* d_in, const int* in_sizes, int n_in,
                              void* d_out, int out_size)
{
    const float* feat = (const float*)d_in[0];   // [N, 128] f32
    const int*   nbr  = (const int*)d_in[1];     // [E] i32
    const int*   sid  = (const int*)d_in[2];     // [E] i32, sorted
    float*       out  = (float*)d_out;           // [N, 128] f32

    const int n_edges = in_sizes[1];
    const int n_nodes = out_size / D_FEAT;

    if (n_nodes <= MAX_NODES) {
        const int n2 = n_nodes * (D_FEAT / 2);
        const int cthreads = 256;
        const int cblocks = (n2 + cthreads - 1) / cthreads;
        convert_f32_to_f16<<<cblocks, cthreads>>>((const float2*)feat, n2);
        const int blocks = (n_nodes + WARPS_PER_BLOCK - 1) / WARPS_PER_BLOCK;
        seg_mean_h16_kernel<<<blocks, 256>>>(nbr, sid, out, n_nodes, n_edges);
    } else {
        const int blocks = (n_nodes + 7) / 8;
        seg_mean_f32_kernel<<<blocks, 256>>>(feat, nbr, sid, out, n_nodes, n_edges);
    }
}

// round 15
// speedup vs baseline: 1.9079x; 1.0527x over previous
#include <cuda_runtime.h>
#include <cuda_fp16.h>
#include <cstdint>

// MeanAggregator: ragged segment-mean, sorted int32 segment_ids.
// fp16-staged features (256B rows), warp-per-node, __ldcg gathers.
// Main loop: 8 independent uint2 gathers in flight (16 payload regs) —
// fp16 is below the LTS bandwidth cap, so deeper MLP should convert
// directly to time (unlike f32, which was cap-bound).

#define D_FEAT 128
#define VEC_PER_ROW (D_FEAT / 4)
#define WARPS_PER_BLOCK 4
#define MAX_NODES 50000

__device__ __half2 g_feat_h2[MAX_NODES * (D_FEAT / 2)];

__global__ void convert_f32_to_f16(const float2* __restrict__ in, int n2)
{
    int i = blockIdx.x * blockDim.x + threadIdx.x;
    if (i < n2) g_feat_h2[i] = __float22half2_rn(in[i]);
}

__device__ __forceinline__ void acc_h2(float4& acc, uint2 v)
{
    float2 a = __half22float2(*(__half2*)&v.x);
    float2 b = __half22float2(*(__half2*)&v.y);
    acc.x += a.x; acc.y += a.y; acc.z += b.x; acc.w += b.y;
}

__global__ void __launch_bounds__(128)
seg_mean_h16_kernel(const int* __restrict__ nbr,
                    const int* __restrict__ sid,
                    float* __restrict__ out,
                    int n_nodes, int n_edges)
{
    __shared__ int bounds[WARPS_PER_BLOCK + 1];

    const int lane = threadIdx.x & 31;
    const int warp = threadIdx.x >> 5;
    const int node_base = blockIdx.x * WARPS_PER_BLOCK;

    if (warp == 0 && lane <= WARPS_PER_BLOCK) {
        const int target = node_base + lane;
        int lo = 0, hi = n_edges;
        while (lo < hi) {
            int mid = (lo + hi) >> 1;
            if (__ldg(&sid[mid]) < target) lo = mid + 1; else hi = mid;
        }
        bounds[lane] = lo;
    }
    __syncthreads();

    const int node = node_base + warp;
    if (node >= n_nodes) return;

    const int start = bounds[warp];
    const int end   = bounds[warp + 1];

    const uint2* __restrict__ featq = (const uint2*)g_feat_h2;

    float4 acc0 = make_float4(0.f, 0.f, 0.f, 0.f);
    float4 acc1 = make_float4(0.f, 0.f, 0.f, 0.f);

    int e = start;
    // 8 independent gathers in flight per iteration.
    for (; e + 8 <= end; e += 8) {
        int i0 = __ldg(&nbr[e]);
        int i1 = __ldg(&nbr[e + 1]);
        int i2 = __ldg(&nbr[e + 2]);
        int i3 = __ldg(&nbr[e + 3]);
        int i4 = __ldg(&nbr[e + 4]);
        int i5 = __ldg(&nbr[e + 5]);
        int i6 = __ldg(&nbr[e + 6]);
        int i7 = __ldg(&nbr[e + 7]);

        uint2 r0 = __ldcg(&featq[i0 * 32 + lane]);
        uint2 r1 = __ldcg(&featq[i1 * 32 + lane]);
        uint2 r2 = __ldcg(&featq[i2 * 32 + lane]);
        uint2 r3 = __ldcg(&featq[i3 * 32 + lane]);
        uint2 r4 = __ldcg(&featq[i4 * 32 + lane]);
        uint2 r5 = __ldcg(&featq[i5 * 32 + lane]);
        uint2 r6 = __ldcg(&featq[i6 * 32 + lane]);
        uint2 r7 = __ldcg(&featq[i7 * 32 + lane]);

        acc_h2(acc0, r0);
        acc_h2(acc1, r1);
        acc_h2(acc0, r2);
        acc_h2(acc1, r3);
        acc_h2(acc0, r4);
        acc_h2(acc1, r5);
        acc_h2(acc0, r6);
        acc_h2(acc1, r7);
    }
    // Mid tail: 4 in flight.
    for (; e + 4 <= end; e += 4) {
        int i0 = __ldg(&nbr[e]);
        int i1 = __ldg(&nbr[e + 1]);
        int i2 = __ldg(&nbr[e + 2]);
        int i3 = __ldg(&nbr[e + 3]);
        uint2 r0 = __ldcg(&featq[i0 * 32 + lane]);
        uint2 r1 = __ldcg(&featq[i1 * 32 + lane]);
        uint2 r2 = __ldcg(&featq[i2 * 32 + lane]);
        uint2 r3 = __ldcg(&featq[i3 * 32 + lane]);
        acc_h2(acc0, r0);
        acc_h2(acc1, r1);
        acc_h2(acc0, r2);
        acc_h2(acc1, r3);
    }
    for (; e < end; e++) {
        int i0 = __ldg(&nbr[e]);
        uint2 r0 = __ldcg(&featq[i0 * 32 + lane]);
        acc_h2(acc0, r0);
    }

    acc0.x += acc1.x; acc0.y += acc1.y; acc0.z += acc1.z; acc0.w += acc1.w;

    const int cnt = end - start;
    const float inv = (cnt > 0) ? (1.0f / (float)cnt) : 0.0f;
    acc0.x *= inv; acc0.y *= inv; acc0.z *= inv; acc0.w *= inv;

    ((float4*)out)[node * VEC_PER_ROW + lane] = acc0;
}

// Fallback f32 path (only if n_nodes exceeds the static fp16 buffer).
__global__ void __launch_bounds__(256)
seg_mean_f32_kernel(const float* __restrict__ feat,
                    const int* __restrict__ nbr,
                    const int* __restrict__ sid,
                    float* __restrict__ out,
                    int n_nodes, int n_edges)
{
    __shared__ int bounds[9];
    const int lane = threadIdx.x & 31;
    const int warp = threadIdx.x >> 5;
    const int node_base = blockIdx.x * 8;

    if (warp == 0 && lane <= 8) {
        const int target = node_base + lane;
        int lo = 0, hi = n_edges;
        while (lo < hi) {
            int mid = (lo + hi) >> 1;
            if (__ldg(&sid[mid]) < target) lo = mid + 1; else hi = mid;
        }
        bounds[lane] = lo;
    }
    __syncthreads();

    const int node = node_base + warp;
    if (node >= n_nodes) return;
    const int start = bounds[warp];
    const int end   = bounds[warp + 1];

    const float4* __restrict__ featv = (const float4*)feat;
    float4 acc0 = make_float4(0.f, 0.f, 0.f, 0.f);
    float4 acc1 = make_float4(0.f, 0.f, 0.f, 0.f);

    int e = start;
    for (; e + 4 <= end; e += 4) {
        int i0 = __ldg(&nbr[e]);
        int i1 = __ldg(&nbr[e + 1]);
        int i2 = __ldg(&nbr[e + 2]);
        int i3 = __ldg(&nbr[e + 3]);
        float4 v0 = __ldg(&featv[i0 * VEC_PER_ROW + lane]);
        float4 v1 = __ldg(&featv[i1 * VEC_PER_ROW + lane]);
        float4 v2 = __ldg(&featv[i2 * VEC_PER_ROW + lane]);
        float4 v3 = __ldg(&featv[i3 * VEC_PER_ROW + lane]);
        acc0.x += v0.x; acc0.y += v0.y; acc0.z += v0.z; acc0.w += v0.w;
        acc1.x += v1.x; acc1.y += v1.y; acc1.z += v1.z; acc1.w += v1.w;
        acc0.x += v2.x; acc0.y += v2.y; acc0.z += v2.z; acc0.w += v2.w;
        acc1.x += v3.x; acc1.y += v3.y; acc1.z += v3.z; acc1.w += v3.w;
    }
    for (; e < end; e++) {
        int i0 = __ldg(&nbr[e]);
        float4 v0 = __ldg(&featv[i0 * VEC_PER_ROW + lane]);
        acc0.x += v0.x; acc0.y += v0.y; acc0.z += v0.z; acc0.w += v0.w;
    }
    acc0.x += acc1.x; acc0.y += acc1.y; acc0.z += acc1.z; acc0.w += acc1.w;

    const int cnt = end - start;
    const float inv = (cnt > 0) ? (1.0f / (float)cnt) : 0.0f;
    acc0.x *= inv; acc0.y *= inv; acc0.z *= inv; acc0.w *= inv;
    ((float4*)out)[node * VEC_PER_ROW + lane] = acc0;
}

extern "C" void kernel_launch(void* const* d_in, const int* in_sizes, int n_in,
                              void* d_out, int out_size)
{
    const float* feat = (const float*)d_in[0];   // [N, 128] f32
    const int*   nbr  = (const int*)d_in[1];     // [E] i32
    const int*   sid  = (const int*)d_in[2];     // [E] i32, sorted
    float*       out  = (float*)d_out;           // [N, 128] f32

    const int n_edges = in_sizes[1];
    const int n_nodes = out_size / D_FEAT;

    if (n_nodes <= MAX_NODES) {
        const int n2 = n_nodes * (D_FEAT / 2);
        const int cthreads = 256;
        const int cblocks = (n2 + cthreads - 1) / cthreads;
        convert_f32_to_f16<<<cblocks, cthreads>>>((const float2*)feat, n2);
        const int blocks = (n_nodes + WARPS_PER_BLOCK - 1) / WARPS_PER_BLOCK;
        seg_mean_h16_kernel<<<blocks, 32 * WARPS_PER_BLOCK>>>(nbr, sid, out,
                                                              n_nodes, n_edges);
    } else {
        const int blocks = (n_nodes + 7) / 8;
        seg_mean_f32_kernel<<<blocks, 256>>>(feat, nbr, sid, out, n_nodes, n_edges);
    }
}